// round 15
// baseline (speedup 1.0000x reference)
#include <cuda_runtime.h>
#include <cuda_bf16.h>
#include <cstdint>

#define NB    16
#define NPTS  4096
#define SPTS  1024
#define COLS  65536
#define JCOLS 16384

// fp32 scratch
__device__ __align__(16) float g_Z[3u * 16384u * 256u];   // Z[k][jcol][o 256]
__device__ __align__(16) float g_Yt[65536u * 256u];       // Y transposed: [col][chan 256]
__device__ __align__(16) float g_O2[128u * 65536u];       // [row][col]
// bf16 split weights, transposed [c][o]
__device__ __align__(16) __nv_bfloat16 g_W0Thi[512 * 256], g_W0Tlo[512 * 256];
__device__ __align__(16) __nv_bfloat16 g_W1Thi[256 * 128], g_W1Tlo[256 * 128];
__device__ int   g_idx[65536 * 3];
__device__ float g_w[65536 * 3];
__device__ float g_sum0[256], g_sq0[256], g_a0[256], g_c0[256];
__device__ float g_sum1[128], g_sq1[128], g_a1[128], g_c1[128];

__device__ __forceinline__ void cp16(uint32_t dst, const void* src) {
    asm volatile("cp.async.ca.shared.global [%0], [%1], 16;\n" :: "r"(dst), "l"(src));
}
__device__ __forceinline__ void cp_commit() { asm volatile("cp.async.commit_group;\n"); }
template<int N> __device__ __forceinline__ void cp_wait() {
    asm volatile("cp.async.wait_group %0;\n" :: "n"(N));
}
__device__ __forceinline__ void ldsm4t(uint32_t* r, uint32_t addr) {
    asm volatile("ldmatrix.sync.aligned.m8n8.x4.trans.shared.b16 {%0,%1,%2,%3}, [%4];"
                 : "=r"(r[0]), "=r"(r[1]), "=r"(r[2]), "=r"(r[3]) : "r"(addr));
}
__device__ __forceinline__ void ldsm2t(uint32_t* r, uint32_t addr) {
    asm volatile("ldmatrix.sync.aligned.m8n8.x2.trans.shared.b16 {%0,%1}, [%2];"
                 : "=r"(r[0]), "=r"(r[1]) : "r"(addr));
}
__device__ __forceinline__ void mma16816(float* d, const uint32_t* a, const uint32_t* b) {
    asm volatile("mma.sync.aligned.m16n8k16.row.col.f32.bf16.bf16.f32 "
                 "{%0,%1,%2,%3}, {%4,%5,%6,%7}, {%8,%9}, {%0,%1,%2,%3};"
                 : "+f"(d[0]), "+f"(d[1]), "+f"(d[2]), "+f"(d[3])
                 : "r"(a[0]), "r"(a[1]), "r"(a[2]), "r"(a[3]), "r"(b[0]), "r"(b[1]));
}
__device__ __forceinline__ uint32_t bf2u(__nv_bfloat16 a, __nv_bfloat16 b) {
    return (uint32_t)__bfloat16_as_ushort(a) | ((uint32_t)__bfloat16_as_ushort(b) << 16);
}
__device__ __forceinline__ void split2(float v0, float v1, uint32_t& hi, uint32_t& lo) {
    const __nv_bfloat16 h0 = __float2bfloat16(v0), h1 = __float2bfloat16(v1);
    hi = bf2u(h0, h1);
    lo = bf2u(__float2bfloat16(v0 - __bfloat162float(h0)),
              __float2bfloat16(v1 - __bfloat162float(h1)));
}

// one k16 compute step: 2 m-atoms x 4 n-atoms, 3 split terms
__device__ __forceinline__ void mma_step(uint32_t sbA, uint32_t sbB, const uint32_t* aoff,
                                         const uint32_t* boff, float acc[2][4][4],
                                         uint32_t ksb) {
    uint32_t ahi[2][4], alo[2][4], bhi[4][2], blo[4][2];
#pragma unroll
    for (int am = 0; am < 2; am++) {
        ldsm4t(ahi[am], sbA + aoff[am] + ksb);
        ldsm4t(alo[am], sbA + 8192 + aoff[am] + ksb);
    }
#pragma unroll
    for (int an = 0; an < 4; an++) {
        ldsm2t(bhi[an], sbB + boff[an] + ksb);
        ldsm2t(blo[an], sbB + 8192 + boff[an] + ksb);
    }
#pragma unroll
    for (int am = 0; am < 2; am++)
#pragma unroll
        for (int an = 0; an < 4; an++) {
            mma16816(acc[am][an], ahi[am], bhi[an]);
            mma16816(acc[am][an], ahi[am], blo[an]);
            mma16816(acc[am][an], alo[am], bhi[an]);
        }
}

__device__ __forceinline__ void frag_offsets(int t, uint32_t* aoff, uint32_t* boff) {
    const int L = t & 31, w = t >> 5;
    const int wm = w >> 2, wn = w & 3;
    const int mtx = L >> 3;
    const int kA = (L & 7) + ((mtx & 2) << 2);
    const int mA = wm * 32 + ((mtx & 1) << 3);
#pragma unroll
    for (int am = 0; am < 2; am++)
        aoff[am] = (uint32_t)(kA * 256 + ((((mA + am * 16) >> 3) ^ (kA & 7)) << 4));
    const int kB = L & 15;
#pragma unroll
    for (int an = 0; an < 4; an++) {
        const int nB = wn * 32 + an * 8;
        boff[an] = (uint32_t)(kB * 256 + (((nB >> 3) ^ (kB & 7)) << 4));
    }
}

// ===== register-loader mainloop (non-TR): B via LDG + reg split + direct STS =====
// smem: A stages 0..2 at (kt%3)*16384 (hi +0, lo +8192); conv B at 49152+(kt&1)*16384.
// One __syncthreads per k-tile. Total smem 81920 B.
template<int A_LD, int B_LD, int NT>
__device__ __forceinline__ void mma_mainR(char* sm,
        const __nv_bfloat16* aHi, const __nv_bfloat16* aLo,
        const float* bF, float acc[2][4][4]) {
    const int t = threadIdx.x;
    const uint32_t sb = (uint32_t)__cvta_generic_to_shared(sm);
    const int lk = t >> 4, lg = t & 15;
    const uint32_t dstA = (uint32_t)(lk * 256 + ((lg ^ (lk & 7)) << 4));
    const uint32_t cOff = dstA;

    uint32_t aoff[2], boff[4];
    frag_offsets(t, aoff, boff);
#pragma unroll
    for (int am = 0; am < 2; am++)
#pragma unroll
        for (int an = 0; an < 4; an++)
#pragma unroll
            for (int d = 0; d < 4; d++) acc[am][an][d] = 0.f;

    float4 bv0, bv1;
    auto ldgB = [&](int kt2) {
        const float* s = bF + ((size_t)kt2 * 32 + lk) * B_LD + lg * 8;
        bv0 = *(const float4*)s;
        bv1 = *(const float4*)(s + 4);
    };
    auto stsB = [&](int kt2) {
        uint32_t hi[4], lo[4];
        split2(bv0.x, bv0.y, hi[0], lo[0]);
        split2(bv0.z, bv0.w, hi[1], lo[1]);
        split2(bv1.x, bv1.y, hi[2], lo[2]);
        split2(bv1.z, bv1.w, hi[3], lo[3]);
        char* cd = sm + 49152 + (kt2 & 1) * 16384 + cOff;
        *(uint4*)cd = make_uint4(hi[0], hi[1], hi[2], hi[3]);
        *(uint4*)(cd + 8192) = make_uint4(lo[0], lo[1], lo[2], lo[3]);
    };
    auto loadA = [&](int kt2) {
        const uint32_t buf = sb + (uint32_t)(kt2 % 3) * 16384;
        const size_t ka = (size_t)kt2 * 32 + lk;
        cp16(buf + dstA, aHi + ka * A_LD + lg * 8);
        cp16(buf + 8192 + dstA, aLo + ka * A_LD + lg * 8);
        cp_commit();
    };

    loadA(0);
    loadA(1);
    ldgB(0); stsB(0);
    if (NT > 1) ldgB(1);

#pragma unroll 1
    for (int kt = 0; kt < NT; kt++) {
        cp_wait<1>();
        __syncthreads();              // publishes conv(kt) + A(kt); orders buffer reuse
        if (kt + 1 < NT) stsB(kt + 1);
        if (kt + 2 < NT) { ldgB(kt + 2); loadA(kt + 2); }
        else cp_commit();
        const uint32_t sA = sb + (uint32_t)(kt % 3) * 16384;
        const uint32_t sB = sb + 49152u + (uint32_t)(kt & 1) * 16384;
        mma_step(sA, sB, aoff, boff, acc, 0);
        mma_step(sA, sB, aoff, boff, acc, 4096);
    }
}

// ===== TR mainloop (gemmO2): 2-stage, B from g_Yt via cp.async + smem transpose =====
// smem: stages 0..1 at (kt&1)*34816 (A hi/lo 16K + raw B 18K); conv at 69632. 86016 B.
template<int A_LD, int B_LD, int NT, bool BN>
__device__ __forceinline__ void mma_mainTR(char* sm,
        const __nv_bfloat16* aHi, const __nv_bfloat16* aLo,
        const float* bF, const float* bnA, const float* bnC,
        float acc[2][4][4]) {
    constexpr int STAGE = 16384 + 18432;
    constexpr int CONVO = 2 * STAGE;
    const int t = threadIdx.x;
    const uint32_t sb = (uint32_t)__cvta_generic_to_shared(sm);
    const int lk = t >> 4, lg = t & 15;
    const uint32_t dstA = (uint32_t)(lk * 256 + ((lg ^ (lk & 7)) << 4));

    uint32_t aoff[2], boff[4];
    frag_offsets(t, aoff, boff);
#pragma unroll
    for (int am = 0; am < 2; am++)
#pragma unroll
        for (int an = 0; an < 4; an++)
#pragma unroll
            for (int d = 0; d < 4; d++) acc[am][an][d] = 0.f;

    auto load_st = [&](int kt2) {
        const uint32_t buf = sb + (uint32_t)(kt2 & 1) * STAGE;
        const size_t ka = (size_t)kt2 * 32 + lk;
        cp16(buf + dstA, aHi + ka * A_LD + lg * 8);
        cp16(buf + 8192 + dstA, aLo + ka * A_LD + lg * 8);
#pragma unroll
        for (int h = 0; h < 2; h++) {
            const int c2 = t * 2 + h;
            const int row = c2 >> 3, seg = c2 & 7;
            cp16(buf + 16384u + (uint32_t)(row * 144 + seg * 16),
                 bF + (size_t)row * B_LD + kt2 * 32 + seg * 4);
        }
        cp_commit();
    };

    auto convert = [&](int ckt) {
        char* conv = sm + CONVO;
        const int k = t & 31, n0 = (t >> 5) * 8;
        const char* raw = sm + (ckt & 1) * STAGE + 16384;
        float v[8];
#pragma unroll
        for (int i = 0; i < 8; i++)
            v[i] = *(const float*)(raw + (n0 + i) * 144 + k * 4);
        if (BN) {
            const float a = bnA[ckt * 32 + k], c = bnC[ckt * 32 + k];
#pragma unroll
            for (int i = 0; i < 8; i++) v[i] = fmaxf(0.f, fmaf(a, v[i], c));
        }
        uint32_t hi[4], lo[4];
#pragma unroll
        for (int j = 0; j < 4; j++) split2(v[2 * j], v[2 * j + 1], hi[j], lo[j]);
        char* cd = conv + k * 256 + (((n0 >> 3) ^ (k & 7)) << 4);
        *(uint4*)cd = make_uint4(hi[0], hi[1], hi[2], hi[3]);
        *(uint4*)(cd + 8192) = make_uint4(lo[0], lo[1], lo[2], lo[3]);
    };

    load_st(0);

#pragma unroll 1
    for (int kt = 0; kt < NT; kt++) {
        cp_wait<0>();
        __syncthreads();              // stage kt arrived; prior conv reads done
        convert(kt);
        __syncthreads();              // conv ready; raw kt consumed
        if (kt + 1 < NT) load_st(kt + 1);
        const uint32_t sA = sb + (uint32_t)(kt & 1) * STAGE;
        const uint32_t sB = sb + CONVO;
        mma_step(sA, sB, aoff, boff, acc, 0);
        mma_step(sA, sB, aoff, boff, acc, 4096);
    }
}

// ---------------- prep: zero stats + split weights (transposed [c][o]) ----------------
__global__ void prep_kernel(const float* __restrict__ w0, const float* __restrict__ w1) {
    const int idx = blockIdx.x * 256 + threadIdx.x;
    if (idx < 256) { g_sum0[idx] = 0.f; g_sq0[idx] = 0.f; }
    if (idx < 128) { g_sum1[idx] = 0.f; g_sq1[idx] = 0.f; }
    if (idx < 512 * 256) {
        const float v = w0[(idx & 255) * 512 + (idx >> 8)];
        const __nv_bfloat16 h = __float2bfloat16(v);
        g_W0Thi[idx] = h;
        g_W0Tlo[idx] = __float2bfloat16(v - __bfloat162float(h));
    }
    if (idx < 256 * 128) {
        const float v = w1[(idx & 127) * 256 + (idx >> 7)];
        const __nv_bfloat16 h = __float2bfloat16(v);
        g_W1Thi[idx] = h;
        g_W1Tlo[idx] = __float2bfloat16(v - __bfloat162float(h));
    }
}

// ---------------- 3-NN search + interpolation weights ----------------
__global__ void knn_kernel(const float* __restrict__ xyz1,
                           const float* __restrict__ xyz2) {
    __shared__ float sx[SPTS], sy[SPTS], sz[SPTS], sn[SPTS];
    const int t = threadIdx.x;
    const int b = blockIdx.x >> 4;
    const int qbase = (blockIdx.x & 15) << 8;
    const float* base2 = xyz2 + (size_t)b * 3 * SPTS;
    for (int i = t; i < SPTS; i += 256) {
        float x = base2[i], y = base2[SPTS + i], z = base2[2 * SPTS + i];
        sx[i] = x; sy[i] = y; sz[i] = z; sn[i] = x * x + y * y + z * z;
    }
    __syncthreads();
    const int n = qbase + t;
    const float* base1 = xyz1 + (size_t)b * 3 * NPTS;
    const float qx = base1[n], qy = base1[NPTS + n], qz = base1[2 * NPTS + n];
    const float qn = qx * qx + qy * qy + qz * qz;
    float d0 = 3.4e38f, d1 = 3.4e38f, d2 = 3.4e38f;
    int i0 = 0, i1 = 0, i2 = 0;
#pragma unroll 4
    for (int s = 0; s < SPTS; s++) {
        float d = qn + sn[s] - 2.f * (qx * sx[s] + qy * sy[s] + qz * sz[s]);
        if (d < d2) {
            if (d < d1) {
                if (d < d0) { d2 = d1; i2 = i1; d1 = d0; i1 = i0; d0 = d; i0 = s; }
                else        { d2 = d1; i2 = i1; d1 = d;  i1 = s; }
            } else          { d2 = d;  i2 = s; }
        }
    }
    const float r0 = 1.f / (d0 + 1e-8f);
    const float r1 = 1.f / (d1 + 1e-8f);
    const float r2 = 1.f / (d2 + 1e-8f);
    const float inv = 1.f / (r0 + r1 + r2);
    const int col = b * NPTS + n;
    g_idx[col * 3 + 0] = i0; g_idx[col * 3 + 1] = i1; g_idx[col * 3 + 2] = i2;
    g_w[col * 3 + 0] = r0 * inv; g_w[col * 3 + 1] = r1 * inv; g_w[col * 3 + 2] = r2 * inv;
}

// frag scatter to TRANSPOSED smem C tile: Ct[n 128][132]
#define FRAGS_TO_CT() \
    __syncthreads(); \
    float* Ct = (float*)sm; \
    { \
        const int L = threadIdx.x & 31, w = threadIdx.x >> 5; \
        const int wm = w >> 2, wn = w & 3; \
        _Pragma("unroll") \
        for (int am = 0; am < 2; am++) \
            _Pragma("unroll") \
            for (int an = 0; an < 4; an++) { \
                const int m = wm * 32 + am * 16 + (L >> 2); \
                const int n = wn * 32 + an * 8 + ((L & 3) << 1); \
                Ct[n * 132 + m]             = acc[am][an][0]; \
                Ct[(n + 1) * 132 + m]       = acc[am][an][1]; \
                Ct[n * 132 + m + 8]         = acc[am][an][2]; \
                Ct[(n + 1) * 132 + m + 8]   = acc[am][an][3]; \
            } \
    } \
    __syncthreads();

// frag scatter to normal C tile [m 128][132] (gemmO2 epilogue)
#define FRAGS_TO_CS() \
    __syncthreads(); \
    float* Cs = (float*)sm; \
    { \
        const int L = threadIdx.x & 31, w = threadIdx.x >> 5; \
        const int wm = w >> 2, wn = w & 3; \
        _Pragma("unroll") \
        for (int am = 0; am < 2; am++) \
            _Pragma("unroll") \
            for (int an = 0; an < 4; an++) { \
                const int m = wm * 32 + am * 16 + (L >> 2); \
                const int n = wn * 32 + an * 8 + ((L & 3) << 1); \
                Cs[m * 132 + n]           = acc[am][an][0]; \
                Cs[m * 132 + n + 1]       = acc[am][an][1]; \
                Cs[(m + 8) * 132 + n]     = acc[am][an][2]; \
                Cs[(m + 8) * 132 + n + 1] = acc[am][an][3]; \
            } \
    } \
    __syncthreads();

#define SMEM_R   81920                 // A 3x16K + conv B 2x16K
#define SMEM_TR  86016                 // 2x34816 + conv 16384

// ---------------- GEMM Z: D[o 128][col 128], K=128; coalesced Z store --------------
__global__ __launch_bounds__(512, 2) void gemmZ_mma(const float* __restrict__ p2) {
    extern __shared__ __align__(16) char sm[];
    const int col0 = blockIdx.x * 128;
    const int kg = blockIdx.y >> 1;
    const int o0 = (blockIdx.y & 1) * 128;
    const int bb = col0 >> 10, sOff = col0 & 1023;

    float acc[2][4][4];
    mma_mainR<256, 1024, 4>(sm,
        g_W0Thi + (size_t)(128 + kg * 128) * 256 + o0,
        g_W0Tlo + (size_t)(128 + kg * 128) * 256 + o0,
        p2 + (size_t)bb * 131072 + sOff, acc);

    FRAGS_TO_CT();

    const int t = threadIdx.x;
    const int L = t & 31, w = t >> 5;
#pragma unroll
    for (int cc = 0; cc < 8; cc++) {
        const int c = w * 8 + cc;
        const int col = col0 + c;
        float4 v = *(const float4*)&Ct[c * 132 + L * 4];
        *(float4*)&g_Z[((size_t)(kg * JCOLS + col)) * 256 + o0 + L * 4] = v;
    }
}

// ---------------- GEMM Y: M=256 (2 y-blocks), K=128; warp-per-col gather ------------
__global__ __launch_bounds__(512, 2) void gemmY_mma(const float* __restrict__ p1,
                                                    const float* __restrict__ bias0) {
    extern __shared__ __align__(16) char sm[];
    const int col0 = blockIdx.x * 128;
    const int m0 = blockIdx.y * 128;
    const int bb = col0 >> 12, nOff = col0 & 4095;

    float acc[2][4][4];
    mma_mainR<256, 4096, 4>(sm,
        g_W0Thi + m0, g_W0Tlo + m0,
        p1 + (size_t)bb * 524288 + nOff, acc);

    FRAGS_TO_CT();

    const int t = threadIdx.x;
    const int L = t & 31, w = t >> 5;
    const float4 bias4 = *(const float4*)&bias0[m0 + L * 4];
    float s4[4] = {0.f, 0.f, 0.f, 0.f}, q4[4] = {0.f, 0.f, 0.f, 0.f};

#pragma unroll
    for (int cc = 0; cc < 8; cc++) {
        const int c = w * 8 + cc;
        const int col = col0 + c;
        float4 v = *(const float4*)&Ct[c * 132 + L * 4];
        const int ia = g_idx[col * 3], ib = g_idx[col * 3 + 1], ic = g_idx[col * 3 + 2];
        const float wa = g_w[col * 3], wb = g_w[col * 3 + 1], wc = g_w[col * 3 + 2];
        const int jb = (col >> 12) << 10;
        float4 z0 = *(const float4*)(g_Z + ((size_t)(jb + ia)) * 256 + m0 + L * 4);
        float4 z1 = *(const float4*)(g_Z + ((size_t)(JCOLS + jb + ib)) * 256 + m0 + L * 4);
        float4 z2 = *(const float4*)(g_Z + ((size_t)(2 * JCOLS + jb + ic)) * 256 + m0 + L * 4);
        v.x += bias4.x + wa * z0.x + wb * z1.x + wc * z2.x;
        v.y += bias4.y + wa * z0.y + wb * z1.y + wc * z2.y;
        v.z += bias4.z + wa * z0.z + wb * z1.z + wc * z2.z;
        v.w += bias4.w + wa * z0.w + wb * z1.w + wc * z2.w;
        *(float4*)&g_Yt[(size_t)col * 256 + m0 + L * 4] = v;
        s4[0] += v.x; s4[1] += v.y; s4[2] += v.z; s4[3] += v.w;
        q4[0] += v.x * v.x; q4[1] += v.y * v.y; q4[2] += v.z * v.z; q4[3] += v.w * v.w;
    }

    __syncthreads();
    float* red = (float*)sm;
#pragma unroll
    for (int r = 0; r < 4; r++) {
        red[w * 128 + L * 4 + r] = s4[r];
        red[2048 + w * 128 + L * 4 + r] = q4[r];
    }
    __syncthreads();
    if (t < 128) {
        float s = 0.f, q = 0.f;
#pragma unroll
        for (int w2 = 0; w2 < 16; w2++) {
            s += red[w2 * 128 + t];
            q += red[2048 + w2 * 128 + t];
        }
        atomicAdd(&g_sum0[m0 + t], s);
        atomicAdd(&g_sq0[m0 + t], q);
    }
}

__global__ void finalize0(const float* __restrict__ gamma, const float* __restrict__ beta) {
    const int t = threadIdx.x;
    const float mean = g_sum0[t] * (1.f / COLS);
    const float var = g_sq0[t] * (1.f / COLS) - mean * mean;
    const float a = gamma[t] * rsqrtf(var + 1e-5f);
    g_a0[t] = a;
    g_c0[t] = beta[t] - mean * a;
}

// ---------------- GEMM O2: M=128, K=256; B from g_Yt (TR), BN0+ReLU fused ------------
__global__ __launch_bounds__(512, 2) void gemmO2_mma(const float* __restrict__ bias1) {
    extern __shared__ __align__(16) char sm[];
    const int col0 = blockIdx.x * 128;

    float acc[2][4][4];
    mma_mainTR<128, 256, 8, true>(sm,
        g_W1Thi, g_W1Tlo,
        g_Yt + (size_t)col0 * 256, g_a0, g_c0, acc);

    FRAGS_TO_CS();

    const int t = threadIdx.x;
    const int tx = t & 15, ty = t >> 4;
    const int rowb = ty * 4;
    const int colT = col0 + tx * 8;
#pragma unroll
    for (int i = 0; i < 4; i++) {
        const int row = rowb + i;
        const float bias = bias1[row];
        float a8[8];
        float4 u0 = *(const float4*)&Cs[row * 132 + tx * 8];
        float4 u1 = *(const float4*)&Cs[row * 132 + tx * 8 + 4];
        a8[0] = u0.x + bias; a8[1] = u0.y + bias; a8[2] = u0.z + bias; a8[3] = u0.w + bias;
        a8[4] = u1.x + bias; a8[5] = u1.y + bias; a8[6] = u1.z + bias; a8[7] = u1.w + bias;
        float* op = g_O2 + (size_t)row * COLS + colT;
        *(float4*)op       = make_float4(a8[0], a8[1], a8[2], a8[3]);
        *(float4*)(op + 4) = make_float4(a8[4], a8[5], a8[6], a8[7]);
        float s = 0.f, q = 0.f;
#pragma unroll
        for (int j = 0; j < 8; j++) { s += a8[j]; q += a8[j] * a8[j]; }
#pragma unroll
        for (int off = 8; off; off >>= 1) {
            s += __shfl_xor_sync(0xffffffffu, s, off);
            q += __shfl_xor_sync(0xffffffffu, q, off);
        }
        if ((t & 15) == 0) { atomicAdd(&g_sum1[row], s); atomicAdd(&g_sq1[row], q); }
    }
}

__global__ void finalize1(const float* __restrict__ gamma, const float* __restrict__ beta) {
    const int t = threadIdx.x;
    const float mean = g_sum1[t] * (1.f / COLS);
    const float var = g_sq1[t] * (1.f / COLS) - mean * mean;
    const float a = gamma[t] * rsqrtf(var + 1e-5f);
    g_a1[t] = a;
    g_c1[t] = beta[t] - mean * a;
}

// ---------------- BN2 + ReLU + transpose store ----------------
__global__ void bnout_kernel(float* __restrict__ out) {
    const int idx = blockIdx.x * 256 + threadIdx.x;
    const int e = idx * 4;
    const int row = e >> 16;
    const int col = e & 65535;
    const int b = col >> 12, n = col & 4095;
    float4 v = *(const float4*)&g_O2[(size_t)row * COLS + col];
    const float a = g_a1[row], c = g_c1[row];
    float4 w;
    w.x = fmaxf(0.f, fmaf(a, v.x, c));
    w.y = fmaxf(0.f, fmaf(a, v.y, c));
    w.z = fmaxf(0.f, fmaf(a, v.z, c));
    w.w = fmaxf(0.f, fmaf(a, v.w, c));
    *(float4*)&out[((size_t)(b * 128 + row)) * 4096 + n] = w;
}

extern "C" void kernel_launch(void* const* d_in, const int* in_sizes, int n_in,
                              void* d_out, int out_size) {
    const float* xyz1 = (const float*)d_in[0];
    const float* xyz2 = (const float*)d_in[1];
    const float* p1   = (const float*)d_in[2];
    const float* p2   = (const float*)d_in[3];
    const float* w0   = (const float*)d_in[4];
    const float* b0   = (const float*)d_in[5];
    const float* g0   = (const float*)d_in[6];
    const float* be0  = (const float*)d_in[7];
    const float* w1   = (const float*)d_in[8];
    const float* b1   = (const float*)d_in[9];
    const float* g1   = (const float*)d_in[10];
    const float* be1  = (const float*)d_in[11];
    float* out = (float*)d_out;

    cudaFuncSetAttribute(gemmZ_mma, cudaFuncAttributeMaxDynamicSharedMemorySize, SMEM_R);
    cudaFuncSetAttribute(gemmY_mma, cudaFuncAttributeMaxDynamicSharedMemorySize, SMEM_R);
    cudaFuncSetAttribute(gemmO2_mma, cudaFuncAttributeMaxDynamicSharedMemorySize, SMEM_TR);

    prep_kernel<<<512, 256>>>(w0, w1);                              // 1
    knn_kernel<<<256, 256>>>(xyz1, xyz2);                           // 2
    gemmZ_mma<<<dim3(JCOLS / 128, 6), 512, SMEM_R>>>(p2);           // 3
    gemmY_mma<<<dim3(COLS / 128, 2), 512, SMEM_R>>>(p1, b0);        // 4
    finalize0<<<1, 256>>>(g0, be0);                                 // 5
    gemmO2_mma<<<COLS / 128, 512, SMEM_TR>>>(b1);                   // 6 (profiled)
    finalize1<<<1, 128>>>(g1, be1);                                 // 7
    bnout_kernel<<<(COLS * 128 / 4) / 256, 256>>>(out);             // 8
}

// round 17
// speedup vs baseline: 1.5723x; 1.5723x over previous
#include <cuda_runtime.h>
#include <cuda_bf16.h>
#include <cstdint>

#define NB    16
#define NPTS  4096
#define SPTS  1024
#define COLS  65536
#define JCOLS 16384

// fp32 scratch
__device__ __align__(16) float g_Z[3u * 16384u * 256u];   // Z[k][jcol][o 256]
__device__ __align__(16) float g_Yt[65536u * 256u];       // Y transposed: [col][chan 256]
__device__ __align__(16) float g_O2[128u * 65536u];       // [row][col]
// bf16 split weights, transposed [c][o]
__device__ __align__(16) __nv_bfloat16 g_W0Thi[512 * 256], g_W0Tlo[512 * 256];
__device__ __align__(16) __nv_bfloat16 g_W1Thi[256 * 128], g_W1Tlo[256 * 128];
__device__ int   g_idx[65536 * 3];
__device__ float g_w[65536 * 3];
__device__ float g_sum0[256], g_sq0[256], g_a0[256], g_c0[256];
__device__ float g_sum1[128], g_sq1[128], g_a1[128], g_c1[128];

__device__ __forceinline__ void cp16(uint32_t dst, const void* src) {
    asm volatile("cp.async.ca.shared.global [%0], [%1], 16;\n" :: "r"(dst), "l"(src));
}
__device__ __forceinline__ void cp_commit() { asm volatile("cp.async.commit_group;\n"); }
template<int N> __device__ __forceinline__ void cp_wait() {
    asm volatile("cp.async.wait_group %0;\n" :: "n"(N));
}
__device__ __forceinline__ void ldsm4t(uint32_t* r, uint32_t addr) {
    asm volatile("ldmatrix.sync.aligned.m8n8.x4.trans.shared.b16 {%0,%1,%2,%3}, [%4];"
                 : "=r"(r[0]), "=r"(r[1]), "=r"(r[2]), "=r"(r[3]) : "r"(addr));
}
__device__ __forceinline__ void ldsm2t(uint32_t* r, uint32_t addr) {
    asm volatile("ldmatrix.sync.aligned.m8n8.x2.trans.shared.b16 {%0,%1}, [%2];"
                 : "=r"(r[0]), "=r"(r[1]) : "r"(addr));
}
__device__ __forceinline__ void mma16816(float* d, const uint32_t* a, const uint32_t* b) {
    asm volatile("mma.sync.aligned.m16n8k16.row.col.f32.bf16.bf16.f32 "
                 "{%0,%1,%2,%3}, {%4,%5,%6,%7}, {%8,%9}, {%0,%1,%2,%3};"
                 : "+f"(d[0]), "+f"(d[1]), "+f"(d[2]), "+f"(d[3])
                 : "r"(a[0]), "r"(a[1]), "r"(a[2]), "r"(a[3]), "r"(b[0]), "r"(b[1]));
}
__device__ __forceinline__ uint32_t bf2u(__nv_bfloat16 a, __nv_bfloat16 b) {
    return (uint32_t)__bfloat16_as_ushort(a) | ((uint32_t)__bfloat16_as_ushort(b) << 16);
}
__device__ __forceinline__ void split2(float v0, float v1, uint32_t& hi, uint32_t& lo) {
    const __nv_bfloat16 h0 = __float2bfloat16(v0), h1 = __float2bfloat16(v1);
    hi = bf2u(h0, h1);
    lo = bf2u(__float2bfloat16(v0 - __bfloat162float(h0)),
              __float2bfloat16(v1 - __bfloat162float(h1)));
}

// ---- 256-thread CTA, tile 128m x 64n: 8 warps, wm = w>>1 (m32), wn = w&1 (n32) ----
// A smem: [k 32][m 128] bf16 swizzled, hi 8K + lo 8K per stage (row stride 256B).
// B conv smem: [k 32][n 64] bf16 swizzled, hi 4K + lo 4K (row stride 128B).

// one k16 compute step: A lo at sbA+8192, B lo at sbB+4096
__device__ __forceinline__ void mma_step(uint32_t sbA, uint32_t sbB, const uint32_t* aoff,
                                         const uint32_t* boff, float acc[2][4][4],
                                         uint32_t ksbA, uint32_t ksbB) {
    uint32_t ahi[2][4], alo[2][4], bhi[4][2], blo[4][2];
#pragma unroll
    for (int am = 0; am < 2; am++) {
        ldsm4t(ahi[am], sbA + aoff[am] + ksbA);
        ldsm4t(alo[am], sbA + 8192 + aoff[am] + ksbA);
    }
#pragma unroll
    for (int an = 0; an < 4; an++) {
        ldsm2t(bhi[an], sbB + boff[an] + ksbB);
        ldsm2t(blo[an], sbB + 4096 + boff[an] + ksbB);
    }
#pragma unroll
    for (int am = 0; am < 2; am++)
#pragma unroll
        for (int an = 0; an < 4; an++) {
            mma16816(acc[am][an], ahi[am], bhi[an]);
            mma16816(acc[am][an], ahi[am], blo[an]);
            mma16816(acc[am][an], alo[am], bhi[an]);
        }
}

__device__ __forceinline__ void frag_offsets(int t, uint32_t* aoff, uint32_t* boff) {
    const int L = t & 31, w = t >> 5;
    const int wm = w >> 1, wn = w & 1;
    const int mtx = L >> 3;
    const int kA = (L & 7) + ((mtx & 2) << 2);
    const int mA = wm * 32 + ((mtx & 1) << 3);
#pragma unroll
    for (int am = 0; am < 2; am++)
        aoff[am] = (uint32_t)(kA * 256 + ((((mA + am * 16) >> 3) ^ (kA & 7)) << 4));
    const int kB = L & 15;
#pragma unroll
    for (int an = 0; an < 4; an++) {
        const int nB = wn * 32 + an * 8;
        boff[an] = (uint32_t)(kB * 128 + (((nB >> 3) ^ (kB & 7)) << 4));
    }
}

// ===== register-loader mainloop (non-TR): B via LDG + reg split + direct STS =====
// smem: A stages 0..2 at (kt%3)*16384; conv B at 49152+(kt&1)*8192. Total 65536 B.
template<int A_LD, int B_LD, int NT>
__device__ __forceinline__ void mma_mainR(char* sm,
        const __nv_bfloat16* aHi, const __nv_bfloat16* aLo,
        const float* bF, float acc[2][4][4]) {
    const int t = threadIdx.x;
    const uint32_t sb = (uint32_t)__cvta_generic_to_shared(sm);
    const int lk = t >> 4, lg = t & 15;                     // A loader (2 k-rows/thread)
    const uint32_t dstA = (uint32_t)(lk * 256 + ((lg ^ (lk & 7)) << 4));
    const int lkB = t >> 3, lgB = t & 7;                    // B loader
    const uint32_t cOff = (uint32_t)(lkB * 128 + ((lgB ^ (lkB & 7)) << 4));

    uint32_t aoff[2], boff[4];
    frag_offsets(t, aoff, boff);
#pragma unroll
    for (int am = 0; am < 2; am++)
#pragma unroll
        for (int an = 0; an < 4; an++)
#pragma unroll
            for (int d = 0; d < 4; d++) acc[am][an][d] = 0.f;

    float4 bv0, bv1;
    auto ldgB = [&](int kt2) {
        const float* s = bF + ((size_t)kt2 * 32 + lkB) * B_LD + lgB * 8;
        bv0 = *(const float4*)s;
        bv1 = *(const float4*)(s + 4);
    };
    auto stsB = [&](int kt2) {
        uint32_t hi[4], lo[4];
        split2(bv0.x, bv0.y, hi[0], lo[0]);
        split2(bv0.z, bv0.w, hi[1], lo[1]);
        split2(bv1.x, bv1.y, hi[2], lo[2]);
        split2(bv1.z, bv1.w, hi[3], lo[3]);
        char* cd = sm + 49152 + (kt2 & 1) * 8192 + cOff;
        *(uint4*)cd = make_uint4(hi[0], hi[1], hi[2], hi[3]);
        *(uint4*)(cd + 4096) = make_uint4(lo[0], lo[1], lo[2], lo[3]);
    };
    auto loadA = [&](int kt2) {
        const uint32_t buf = sb + (uint32_t)(kt2 % 3) * 16384;
        const size_t ka = (size_t)kt2 * 32 + lk;
        cp16(buf + dstA, aHi + ka * A_LD + lg * 8);
        cp16(buf + 8192 + dstA, aLo + ka * A_LD + lg * 8);
        cp16(buf + 4096 + dstA, aHi + (ka + 16) * A_LD + lg * 8);
        cp16(buf + 12288 + dstA, aLo + (ka + 16) * A_LD + lg * 8);
        cp_commit();
    };

    loadA(0);
    loadA(1);
    ldgB(0); stsB(0);
    if (NT > 1) ldgB(1);

#pragma unroll 1
    for (int kt = 0; kt < NT; kt++) {
        cp_wait<1>();
        __syncthreads();              // publishes conv(kt) + A(kt); orders buffer reuse
        if (kt + 1 < NT) stsB(kt + 1);
        if (kt + 2 < NT) { ldgB(kt + 2); loadA(kt + 2); }
        else cp_commit();
        const uint32_t sA = sb + (uint32_t)(kt % 3) * 16384;
        const uint32_t sB = sb + 49152u + (uint32_t)(kt & 1) * 8192;
        mma_step(sA, sB, aoff, boff, acc, 0, 0);
        mma_step(sA, sB, aoff, boff, acc, 4096, 2048);
    }
}

// ===== TR mainloop (gemmO2): 2-stage, B from g_Yt via cp.async + smem transpose =====
// stage = A 16K + raw B 64 rows*144B = 9216 -> 25600; stages at (kt&1)*25600;
// conv at 51200 (hi 4K + lo 4K). Total 59392 B.
template<int A_LD, int B_LD, int NT, bool BN>
__device__ __forceinline__ void mma_mainTR(char* sm,
        const __nv_bfloat16* aHi, const __nv_bfloat16* aLo,
        const float* bF, const float* bnA, const float* bnC,
        float acc[2][4][4]) {
    constexpr int STAGE = 16384 + 9216;
    constexpr int CONVO = 2 * STAGE;
    const int t = threadIdx.x;
    const uint32_t sb = (uint32_t)__cvta_generic_to_shared(sm);
    const int lk = t >> 4, lg = t & 15;
    const uint32_t dstA = (uint32_t)(lk * 256 + ((lg ^ (lk & 7)) << 4));

    uint32_t aoff[2], boff[4];
    frag_offsets(t, aoff, boff);
#pragma unroll
    for (int am = 0; am < 2; am++)
#pragma unroll
        for (int an = 0; an < 4; an++)
#pragma unroll
            for (int d = 0; d < 4; d++) acc[am][an][d] = 0.f;

    auto load_st = [&](int kt2) {
        const uint32_t buf = sb + (uint32_t)(kt2 & 1) * STAGE;
        const size_t ka = (size_t)kt2 * 32 + lk;
        cp16(buf + dstA, aHi + ka * A_LD + lg * 8);
        cp16(buf + 8192 + dstA, aLo + ka * A_LD + lg * 8);
        cp16(buf + 4096 + dstA, aHi + (ka + 16) * A_LD + lg * 8);
        cp16(buf + 12288 + dstA, aLo + (ka + 16) * A_LD + lg * 8);
#pragma unroll
        for (int h = 0; h < 2; h++) {
            const int c2 = t + h * 256;
            const int row = c2 >> 3, seg = c2 & 7;
            cp16(buf + 16384u + (uint32_t)(row * 144 + seg * 16),
                 bF + (size_t)row * B_LD + kt2 * 32 + seg * 4);
        }
        cp_commit();
    };

    auto convert = [&](int ckt) {
        char* conv = sm + CONVO;
        const int k = t & 31, n0 = (t >> 5) * 8;
        const char* raw = sm + (ckt & 1) * STAGE + 16384;
        float v[8];
#pragma unroll
        for (int i = 0; i < 8; i++)
            v[i] = *(const float*)(raw + (n0 + i) * 144 + k * 4);
        if (BN) {
            const float a = bnA[ckt * 32 + k], c = bnC[ckt * 32 + k];
#pragma unroll
            for (int i = 0; i < 8; i++) v[i] = fmaxf(0.f, fmaf(a, v[i], c));
        }
        uint32_t hi[4], lo[4];
#pragma unroll
        for (int j = 0; j < 4; j++) split2(v[2 * j], v[2 * j + 1], hi[j], lo[j]);
        char* cd = conv + k * 128 + (((n0 >> 3) ^ (k & 7)) << 4);
        *(uint4*)cd = make_uint4(hi[0], hi[1], hi[2], hi[3]);
        *(uint4*)(cd + 4096) = make_uint4(lo[0], lo[1], lo[2], lo[3]);
    };

    load_st(0);

#pragma unroll 1
    for (int kt = 0; kt < NT; kt++) {
        cp_wait<0>();
        __syncthreads();              // stage kt arrived; prior conv reads done
        convert(kt);
        __syncthreads();              // conv ready; raw kt consumed
        if (kt + 1 < NT) load_st(kt + 1);
        const uint32_t sA = sb + (uint32_t)(kt & 1) * STAGE;
        const uint32_t sB = sb + CONVO;
        mma_step(sA, sB, aoff, boff, acc, 0, 0);
        mma_step(sA, sB, aoff, boff, acc, 4096, 2048);
    }
}

// ---------------- prep: zero stats + split weights (transposed [c][o]) ----------------
__global__ void prep_kernel(const float* __restrict__ w0, const float* __restrict__ w1) {
    const int idx = blockIdx.x * 256 + threadIdx.x;
    if (idx < 256) { g_sum0[idx] = 0.f; g_sq0[idx] = 0.f; }
    if (idx < 128) { g_sum1[idx] = 0.f; g_sq1[idx] = 0.f; }
    if (idx < 512 * 256) {
        const float v = w0[(idx & 255) * 512 + (idx >> 8)];
        const __nv_bfloat16 h = __float2bfloat16(v);
        g_W0Thi[idx] = h;
        g_W0Tlo[idx] = __float2bfloat16(v - __bfloat162float(h));
    }
    if (idx < 256 * 128) {
        const float v = w1[(idx & 127) * 256 + (idx >> 7)];
        const __nv_bfloat16 h = __float2bfloat16(v);
        g_W1Thi[idx] = h;
        g_W1Tlo[idx] = __float2bfloat16(v - __bfloat162float(h));
    }
}

// ---------------- 3-NN search + interpolation weights ----------------
__global__ void knn_kernel(const float* __restrict__ xyz1,
                           const float* __restrict__ xyz2) {
    __shared__ float sx[SPTS], sy[SPTS], sz[SPTS], sn[SPTS];
    const int t = threadIdx.x;
    const int b = blockIdx.x >> 4;
    const int qbase = (blockIdx.x & 15) << 8;
    const float* base2 = xyz2 + (size_t)b * 3 * SPTS;
    for (int i = t; i < SPTS; i += 256) {
        float x = base2[i], y = base2[SPTS + i], z = base2[2 * SPTS + i];
        sx[i] = x; sy[i] = y; sz[i] = z; sn[i] = x * x + y * y + z * z;
    }
    __syncthreads();
    const int n = qbase + t;
    const float* base1 = xyz1 + (size_t)b * 3 * NPTS;
    const float qx = base1[n], qy = base1[NPTS + n], qz = base1[2 * NPTS + n];
    const float qn = qx * qx + qy * qy + qz * qz;
    float d0 = 3.4e38f, d1 = 3.4e38f, d2 = 3.4e38f;
    int i0 = 0, i1 = 0, i2 = 0;
#pragma unroll 4
    for (int s = 0; s < SPTS; s++) {
        float d = qn + sn[s] - 2.f * (qx * sx[s] + qy * sy[s] + qz * sz[s]);
        if (d < d2) {
            if (d < d1) {
                if (d < d0) { d2 = d1; i2 = i1; d1 = d0; i1 = i0; d0 = d; i0 = s; }
                else        { d2 = d1; i2 = i1; d1 = d;  i1 = s; }
            } else          { d2 = d;  i2 = s; }
        }
    }
    const float r0 = 1.f / (d0 + 1e-8f);
    const float r1 = 1.f / (d1 + 1e-8f);
    const float r2 = 1.f / (d2 + 1e-8f);
    const float inv = 1.f / (r0 + r1 + r2);
    const int col = b * NPTS + n;
    g_idx[col * 3 + 0] = i0; g_idx[col * 3 + 1] = i1; g_idx[col * 3 + 2] = i2;
    g_w[col * 3 + 0] = r0 * inv; g_w[col * 3 + 1] = r1 * inv; g_w[col * 3 + 2] = r2 * inv;
}

// frag scatter to TRANSPOSED smem C tile: Ct[n 64][132]
#define FRAGS_TO_CT() \
    __syncthreads(); \
    float* Ct = (float*)sm; \
    { \
        const int L = threadIdx.x & 31, w = threadIdx.x >> 5; \
        const int wm = w >> 1, wn = w & 1; \
        _Pragma("unroll") \
        for (int am = 0; am < 2; am++) \
            _Pragma("unroll") \
            for (int an = 0; an < 4; an++) { \
                const int m = wm * 32 + am * 16 + (L >> 2); \
                const int n = wn * 32 + an * 8 + ((L & 3) << 1); \
                Ct[n * 132 + m]             = acc[am][an][0]; \
                Ct[(n + 1) * 132 + m]       = acc[am][an][1]; \
                Ct[n * 132 + m + 8]         = acc[am][an][2]; \
                Ct[(n + 1) * 132 + m + 8]   = acc[am][an][3]; \
            } \
    } \
    __syncthreads();

// frag scatter to normal C tile [m 128][68] (gemmO2 epilogue)
#define FRAGS_TO_CS() \
    __syncthreads(); \
    float* Cs = (float*)sm; \
    { \
        const int L = threadIdx.x & 31, w = threadIdx.x >> 5; \
        const int wm = w >> 1, wn = w & 1; \
        _Pragma("unroll") \
        for (int am = 0; am < 2; am++) \
            _Pragma("unroll") \
            for (int an = 0; an < 4; an++) { \
                const int m = wm * 32 + am * 16 + (L >> 2); \
                const int n = wn * 32 + an * 8 + ((L & 3) << 1); \
                Cs[m * 68 + n]           = acc[am][an][0]; \
                Cs[m * 68 + n + 1]       = acc[am][an][1]; \
                Cs[(m + 8) * 68 + n]     = acc[am][an][2]; \
                Cs[(m + 8) * 68 + n + 1] = acc[am][an][3]; \
            } \
    } \
    __syncthreads();

#define SMEM_R   65536                 // A 3x16K + conv B 2x8K
#define SMEM_TR  59392                 // 2x25600 + conv 8192

// ---------------- GEMM Z: D[o 128][col 64], K=128; coalesced Z store --------------
__global__ __launch_bounds__(256, 2) void gemmZ_mma(const float* __restrict__ p2) {
    extern __shared__ __align__(16) char sm[];
    const int col0 = blockIdx.x * 64;
    const int kg = blockIdx.y >> 1;
    const int o0 = (blockIdx.y & 1) * 128;
    const int bb = col0 >> 10, sOff = col0 & 1023;

    float acc[2][4][4];
    mma_mainR<256, 1024, 4>(sm,
        g_W0Thi + (size_t)(128 + kg * 128) * 256 + o0,
        g_W0Tlo + (size_t)(128 + kg * 128) * 256 + o0,
        p2 + (size_t)bb * 131072 + sOff, acc);

    FRAGS_TO_CT();

    const int t = threadIdx.x;
    const int L = t & 31, w = t >> 5;
#pragma unroll
    for (int cc = 0; cc < 8; cc++) {
        const int c = w * 8 + cc;
        const int col = col0 + c;
        float4 v = *(const float4*)&Ct[c * 132 + L * 4];
        *(float4*)&g_Z[((size_t)(kg * JCOLS + col)) * 256 + o0 + L * 4] = v;
    }
}

// ---------------- GEMM Y: M=256 (2 y-blocks), K=128; warp-per-col gather ------------
__global__ __launch_bounds__(256, 2) void gemmY_mma(const float* __restrict__ p1,
                                                    const float* __restrict__ bias0) {
    extern __shared__ __align__(16) char sm[];
    const int col0 = blockIdx.x * 64;
    const int m0 = blockIdx.y * 128;
    const int bb = col0 >> 12, nOff = col0 & 4095;

    float acc[2][4][4];
    mma_mainR<256, 4096, 4>(sm,
        g_W0Thi + m0, g_W0Tlo + m0,
        p1 + (size_t)bb * 524288 + nOff, acc);

    FRAGS_TO_CT();

    const int t = threadIdx.x;
    const int L = t & 31, w = t >> 5;
    const float4 bias4 = *(const float4*)&bias0[m0 + L * 4];
    float s4[4] = {0.f, 0.f, 0.f, 0.f}, q4[4] = {0.f, 0.f, 0.f, 0.f};

#pragma unroll
    for (int cc = 0; cc < 8; cc++) {
        const int c = w * 8 + cc;
        const int col = col0 + c;
        float4 v = *(const float4*)&Ct[c * 132 + L * 4];
        const int ia = g_idx[col * 3], ib = g_idx[col * 3 + 1], ic = g_idx[col * 3 + 2];
        const float wa = g_w[col * 3], wb = g_w[col * 3 + 1], wc = g_w[col * 3 + 2];
        const int jb = (col >> 12) << 10;
        float4 z0 = *(const float4*)(g_Z + ((size_t)(jb + ia)) * 256 + m0 + L * 4);
        float4 z1 = *(const float4*)(g_Z + ((size_t)(JCOLS + jb + ib)) * 256 + m0 + L * 4);
        float4 z2 = *(const float4*)(g_Z + ((size_t)(2 * JCOLS + jb + ic)) * 256 + m0 + L * 4);
        v.x += bias4.x + wa * z0.x + wb * z1.x + wc * z2.x;
        v.y += bias4.y + wa * z0.y + wb * z1.y + wc * z2.y;
        v.z += bias4.z + wa * z0.z + wb * z1.z + wc * z2.z;
        v.w += bias4.w + wa * z0.w + wb * z1.w + wc * z2.w;
        *(float4*)&g_Yt[(size_t)col * 256 + m0 + L * 4] = v;
        s4[0] += v.x; s4[1] += v.y; s4[2] += v.z; s4[3] += v.w;
        q4[0] += v.x * v.x; q4[1] += v.y * v.y; q4[2] += v.z * v.z; q4[3] += v.w * v.w;
    }

    __syncthreads();
    float* red = (float*)sm;            // [8][128] sums, [8][128] sq at +1024
#pragma unroll
    for (int r = 0; r < 4; r++) {
        red[w * 128 + L * 4 + r] = s4[r];
        red[1024 + w * 128 + L * 4 + r] = q4[r];
    }
    __syncthreads();
    if (t < 128) {
        float s = 0.f, q = 0.f;
#pragma unroll
        for (int w2 = 0; w2 < 8; w2++) {
            s += red[w2 * 128 + t];
            q += red[1024 + w2 * 128 + t];
        }
        atomicAdd(&g_sum0[m0 + t], s);
        atomicAdd(&g_sq0[m0 + t], q);
    }
}

__global__ void finalize0(const float* __restrict__ gamma, const float* __restrict__ beta) {
    const int t = threadIdx.x;
    const float mean = g_sum0[t] * (1.f / COLS);
    const float var = g_sq0[t] * (1.f / COLS) - mean * mean;
    const float a = gamma[t] * rsqrtf(var + 1e-5f);
    g_a0[t] = a;
    g_c0[t] = beta[t] - mean * a;
}

// ---------------- GEMM O2: M=128, K=256; B from g_Yt (TR), BN0+ReLU fused ------------
__global__ __launch_bounds__(256, 2) void gemmO2_mma(const float* __restrict__ bias1) {
    extern __shared__ __align__(16) char sm[];
    const int col0 = blockIdx.x * 64;

    float acc[2][4][4];
    mma_mainTR<128, 256, 8, true>(sm,
        g_W1Thi, g_W1Tlo,
        g_Yt + (size_t)col0 * 256, g_a0, g_c0, acc);

    FRAGS_TO_CS();

    const int t = threadIdx.x;
    const int tx = t & 7, ty = t >> 3;
    const int rowb = ty * 4;
    const int colT = col0 + tx * 8;
#pragma unroll
    for (int i = 0; i < 4; i++) {
        const int row = rowb + i;
        const float bias = bias1[row];
        float a8[8];
        float4 u0 = *(const float4*)&Cs[row * 68 + tx * 8];
        float4 u1 = *(const float4*)&Cs[row * 68 + tx * 8 + 4];
        a8[0] = u0.x + bias; a8[1] = u0.y + bias; a8[2] = u0.z + bias; a8[3] = u0.w + bias;
        a8[4] = u1.x + bias; a8[5] = u1.y + bias; a8[6] = u1.z + bias; a8[7] = u1.w + bias;
        float* op = g_O2 + (size_t)row * COLS + colT;
        *(float4*)op       = make_float4(a8[0], a8[1], a8[2], a8[3]);
        *(float4*)(op + 4) = make_float4(a8[4], a8[5], a8[6], a8[7]);
        float s = 0.f, q = 0.f;
#pragma unroll
        for (int j = 0; j < 8; j++) { s += a8[j]; q += a8[j] * a8[j]; }
#pragma unroll
        for (int off = 4; off; off >>= 1) {
            s += __shfl_xor_sync(0xffffffffu, s, off);
            q += __shfl_xor_sync(0xffffffffu, q, off);
        }
        if ((t & 7) == 0) { atomicAdd(&g_sum1[row], s); atomicAdd(&g_sq1[row], q); }
    }
}

__global__ void finalize1(const float* __restrict__ gamma, const float* __restrict__ beta) {
    const int t = threadIdx.x;
    const float mean = g_sum1[t] * (1.f / COLS);
    const float var = g_sq1[t] * (1.f / COLS) - mean * mean;
    const float a = gamma[t] * rsqrtf(var + 1e-5f);
    g_a1[t] = a;
    g_c1[t] = beta[t] - mean * a;
}

// ---------------- BN2 + ReLU + transpose store ----------------
__global__ void bnout_kernel(float* __restrict__ out) {
    const int idx = blockIdx.x * 256 + threadIdx.x;
    const int e = idx * 4;
    const int row = e >> 16;
    const int col = e & 65535;
    const int b = col >> 12, n = col & 4095;
    float4 v = *(const float4*)&g_O2[(size_t)row * COLS + col];
    const float a = g_a1[row], c = g_c1[row];
    float4 w;
    w.x = fmaxf(0.f, fmaf(a, v.x, c));
    w.y = fmaxf(0.f, fmaf(a, v.y, c));
    w.z = fmaxf(0.f, fmaf(a, v.z, c));
    w.w = fmaxf(0.f, fmaf(a, v.w, c));
    *(float4*)&out[((size_t)(b * 128 + row)) * 4096 + n] = w;
}

extern "C" void kernel_launch(void* const* d_in, const int* in_sizes, int n_in,
                              void* d_out, int out_size) {
    const float* xyz1 = (const float*)d_in[0];
    const float* xyz2 = (const float*)d_in[1];
    const float* p1   = (const float*)d_in[2];
    const float* p2   = (const float*)d_in[3];
    const float* w0   = (const float*)d_in[4];
    const float* b0   = (const float*)d_in[5];
    const float* g0   = (const float*)d_in[6];
    const float* be0  = (const float*)d_in[7];
    const float* w1   = (const float*)d_in[8];
    const float* b1   = (const float*)d_in[9];
    const float* g1   = (const float*)d_in[10];
    const float* be1  = (const float*)d_in[11];
    float* out = (float*)d_out;

    cudaFuncSetAttribute(gemmZ_mma, cudaFuncAttributeMaxDynamicSharedMemorySize, SMEM_R);
    cudaFuncSetAttribute(gemmY_mma, cudaFuncAttributeMaxDynamicSharedMemorySize, SMEM_R);
    cudaFuncSetAttribute(gemmO2_mma, cudaFuncAttributeMaxDynamicSharedMemorySize, SMEM_TR);

    prep_kernel<<<512, 256>>>(w0, w1);                              // 1
    knn_kernel<<<256, 256>>>(xyz1, xyz2);                           // 2
    gemmZ_mma<<<dim3(JCOLS / 64, 6), 256, SMEM_R>>>(p2);            // 3
    gemmY_mma<<<dim3(COLS / 64, 2), 256, SMEM_R>>>(p1, b0);         // 4
    finalize0<<<1, 256>>>(g0, be0);                                 // 5
    gemmO2_mma<<<COLS / 64, 256, SMEM_TR>>>(b1);                    // 6 (profiled)
    finalize1<<<1, 128>>>(g1, be1);                                 // 7
    bnout_kernel<<<(COLS * 128 / 4) / 256, 256>>>(out);             // 8
}